// round 6
// baseline (speedup 1.0000x reference)
#include <cuda_runtime.h>
#include <cstdint>

#define BATCH 32
#define CIN   3
#define HH    64
#define WW    64
#define HC    128
#define NCTA  128
#define NTHR  256
#define CLU   4

// smem layout (floats). Two h tiles (double buffer), weights, input weights.
#define A0_OFF 0                    // (WW+1) x HC = 65*128 = 8320, row 0 = zero pad (w=-1)
#define A1_OFF 8320
#define W_OFF  16640                // 256 x 128: [(tap*128+ci)*128 + j_*8 + g*2 + p]
#define WI_OFF 49408                // 6 x 128:   [(tap*3+cn)*128 + j_*8 + g*2 + p]
#define SMEM_FLOATS 50176           // 200704 bytes

__device__ __forceinline__ unsigned long long pack2(float lo, float hi) {
    unsigned long long r;
    asm("mov.b64 %0, {%1, %2};" : "=l"(r) : "f"(lo), "f"(hi));
    return r;
}
__device__ __forceinline__ void unpack2(unsigned long long v, float& lo, float& hi) {
    asm("mov.b64 {%0, %1}, %2;" : "=f"(lo), "=f"(hi) : "l"(v));
}
__device__ __forceinline__ unsigned long long fma2(unsigned long long a,
                                                   unsigned long long b,
                                                   unsigned long long c) {
    unsigned long long d;
    asm("fma.rn.f32x2 %0, %1, %2, %3;" : "=l"(d) : "l"(a), "l"(b), "l"(c));
    return d;
}
__device__ __forceinline__ unsigned long long add2(unsigned long long a,
                                                   unsigned long long b) {
    unsigned long long d;
    asm("add.rn.f32x2 %0, %1, %2;" : "=l"(d) : "l"(a), "l"(b));
    return d;
}
__device__ __forceinline__ float sigm(float v) { return 1.f / (1.f + __expf(-v)); }

__global__ __launch_bounds__(NTHR, 1) __cluster_dims__(CLU, 1, 1)
void rowlstm_kernel(const float* __restrict__ x,
                    const float* __restrict__ W_is,
                    const float* __restrict__ b_is,
                    const float* __restrict__ W_ss,
                    const float* __restrict__ b_ss,
                    const float* __restrict__ h0,
                    const float* __restrict__ c0,
                    float* __restrict__ out)
{
    extern __shared__ float sm[];
    float* W_s  = sm + W_OFF;
    float* WI_s = sm + WI_OFF;

    const int tid = threadIdx.x;
    const int b   = blockIdx.x >> 2;
    unsigned int rank;
    asm("mov.u32 %0, %%cluster_ctarank;" : "=r"(rank));
    const int t = (int)rank;                 // ci-tile 0..3

    // ---- one-time loads ----
    // W_s[(tap*128+ci)*128 + j_*8 + g*2 + p], col = g*32 + j_*2 + p (thread-contiguous)
    for (int idx = tid; idx < 32768; idx += NTHR) {
        int k = idx >> 7, r = idx & 127;
        int tap = k >> 7, ci = k & 127;
        int jj = r >> 3, q = r & 7;
        int g = q >> 1, p = q & 1;
        int co = g * HC + t * 32 + jj * 2 + p;
        W_s[idx] = W_ss[(co * HC + ci) * 3 + tap];
    }
    // WI_s[(tap*3+cn)*128 + j_*8 + g*2 + p]
    for (int idx = tid; idx < 768; idx += NTHR) {
        int k = idx >> 7, r = idx & 127;
        int tap = k / 3, cn = k - tap * 3;
        int jj = r >> 3, q = r & 7;
        int g = q >> 1, p = q & 1;
        int co = g * HC + t * 32 + jj * 2 + p;
        WI_s[idx] = W_is[(co * CIN + cn) * 3 + tap];
    }
    // A0 <- full h0 (all 128 ci), both pad rows zero
    for (int idx = tid; idx < 8192; idx += NTHR) {
        int w = idx >> 7, ci = idx & 127;
        sm[A0_OFF + (w + 1) * HC + ci] = h0[ci * WW + w];
    }
    for (int idx = tid; idx < HC; idx += NTHR) {
        sm[A0_OFF + idx] = 0.f;
        sm[A1_OFF + idx] = 0.f;
    }

    const int i_ = tid >> 4;          // 0..15 -> w lanes: w = wi*16 + i_
    const int j_ = tid & 15;          // 0..15 -> ci pair j2 = 2*j_
    const int j2 = j_ << 1;
    const int j8 = j_ << 3;

    // per-thread persistent state: bias pairs + cell state registers
    unsigned long long bias2[4];
    #pragma unroll
    for (int g = 0; g < 4; g++) {
        int co = g * HC + t * 32 + j2;
        bias2[g] = pack2(b_is[co] + b_ss[co], b_is[co + 1] + b_ss[co + 1]);
    }
    float creg[4][2];
    #pragma unroll
    for (int wi = 0; wi < 4; wi++) {
        int w = wi * 16 + i_;
        creg[wi][0] = c0[(t * 32 + j2) * WW + w];
        creg[wi][1] = c0[(t * 32 + j2 + 1) * WW + w];
    }

    // peer smem base addresses (shared::cluster window) for DSMEM h exchange
    unsigned int mybase;
    asm("{ .reg .u64 a; cvta.to.shared.u64 a, %1; cvt.u32.u64 %0, a; }"
        : "=r"(mybase) : "l"(sm));
    unsigned int peer[CLU];
    #pragma unroll
    for (int r = 0; r < CLU; r++)
        asm("mapa.shared::cluster.u32 %0, %1, %2;" : "=r"(peer[r]) : "r"(mybase), "r"(r));

    __syncthreads();   // local init (W_s, WI_s, A0) visible block-wide

    for (int s = 0; s < HH; s++) {
        const float* Ac = sm + ((s & 1) ? A1_OFF : A0_OFF);
        const unsigned int nextOffB = (unsigned int)(((s & 1) ? A0_OFF : A1_OFF) * 4);

        // ---- x-projection (3 cin x 2 taps) + bias FIRST: its LDGs overlap the GEMM ----
        float xr[4][3][2];
        #pragma unroll
        for (int wi = 0; wi < 4; wi++) {
            int w = wi * 16 + i_;
            #pragma unroll
            for (int cn = 0; cn < CIN; cn++) {
                const float* xb = x + ((b * CIN + cn) * HH + s) * WW;
                xr[wi][cn][0] = (w > 0) ? xb[w - 1] : 0.f;
                xr[wi][cn][1] = xb[w];
            }
        }
        unsigned long long xadd[4][4];
        #pragma unroll
        for (int wi = 0; wi < 4; wi++)
            #pragma unroll
            for (int g = 0; g < 4; g++) xadd[wi][g] = bias2[g];
        #pragma unroll
        for (int tap = 0; tap < 2; tap++)
            #pragma unroll
            for (int cn = 0; cn < CIN; cn++) {
                const float* wr = WI_s + (tap * 3 + cn) * 128 + j8;
                ulonglong2 wa = *(const ulonglong2*)wr;        // gates 0,1
                ulonglong2 wb2 = *(const ulonglong2*)(wr + 4); // gates 2,3
                #pragma unroll
                for (int wi = 0; wi < 4; wi++) {
                    unsigned long long xp = pack2(xr[wi][cn][tap], xr[wi][cn][tap]);
                    xadd[wi][0] = fma2(xp, wa.x,  xadd[wi][0]);
                    xadd[wi][1] = fma2(xp, wa.y,  xadd[wi][1]);
                    xadd[wi][2] = fma2(xp, wb2.x, xadd[wi][2]);
                    xadd[wi][3] = fma2(xp, wb2.y, xadd[wi][3]);
                }
            }

        // ---- GEMM: gates for (4 w) x (4 gates x 2 ci) over K = 2 taps x 128 ci ----
        unsigned long long acc[4][4];
        #pragma unroll
        for (int wi = 0; wi < 4; wi++)
            #pragma unroll
            for (int g = 0; g < 4; g++) acc[wi][g] = 0ULL;

        #pragma unroll 2
        for (int cb = 0; cb < HC; cb += 4) {
            float4 aL4[4], aC4[4];
            #pragma unroll
            for (int wi = 0; wi < 4; wi++) {
                int wp = wi * 16 + i_;
                aL4[wi] = *(const float4*)(Ac + wp * HC + cb);
                aC4[wi] = *(const float4*)(Ac + (wp + 1) * HC + cb);
            }
            #pragma unroll
            for (int u = 0; u < 4; u++) {
                const float* wr0 = W_s + (cb + u) * 128 + j8;
                const float* wr1 = wr0 + 128 * 128;
                ulonglong2 w0a = *(const ulonglong2*)wr0;        // tap0 gates 0,1
                ulonglong2 w0b = *(const ulonglong2*)(wr0 + 4);  // tap0 gates 2,3
                ulonglong2 w1a = *(const ulonglong2*)wr1;        // tap1 gates 0,1
                ulonglong2 w1b = *(const ulonglong2*)(wr1 + 4);  // tap1 gates 2,3
                #pragma unroll
                for (int wi = 0; wi < 4; wi++) {
                    float aL = ((const float*)&aL4[wi])[u];
                    float aC = ((const float*)&aC4[wi])[u];
                    unsigned long long aLp = pack2(aL, aL);
                    unsigned long long aCp = pack2(aC, aC);
                    acc[wi][0] = fma2(aLp, w0a.x, acc[wi][0]);
                    acc[wi][1] = fma2(aLp, w0a.y, acc[wi][1]);
                    acc[wi][2] = fma2(aLp, w0b.x, acc[wi][2]);
                    acc[wi][3] = fma2(aLp, w0b.y, acc[wi][3]);
                    acc[wi][0] = fma2(aCp, w1a.x, acc[wi][0]);
                    acc[wi][1] = fma2(aCp, w1a.y, acc[wi][1]);
                    acc[wi][2] = fma2(aCp, w1b.x, acc[wi][2]);
                    acc[wi][3] = fma2(aCp, w1b.y, acc[wi][3]);
                }
            }
        }

        // ---- gates -> c,h in registers; write out + h to all 4 cluster CTAs ----
        #pragma unroll
        for (int wi = 0; wi < 4; wi++) {
            int w = wi * 16 + i_;
            float gv[4][2];
            #pragma unroll
            for (int g = 0; g < 4; g++) {
                float a0, a1;
                unpack2(add2(acc[wi][g], xadd[wi][g]), a0, a1);
                gv[g][0] = sigm(a0);
                gv[g][1] = sigm(a1);
            }
            float hp[2];
            #pragma unroll
            for (int p = 0; p < 2; p++) {
                float cn2 = gv[1][p] * creg[wi][p] + gv[2][p] * gv[3][p];
                creg[wi][p] = cn2;
                float h = gv[0][p] * tanhf(cn2);
                hp[p] = h;
                out[((b * HC + t * 32 + j2 + p) * HH + s) * WW + w] = h;
            }
            unsigned long long hpair = pack2(hp[0], hp[1]);
            unsigned int off = nextOffB + (unsigned int)(((w + 1) * HC + t * 32 + j2) * 4);
            #pragma unroll
            for (int r = 0; r < CLU; r++)
                asm volatile("st.shared::cluster.b64 [%0], %1;"
                             :: "r"(peer[r] + off), "l"(hpair) : "memory");
        }

        // one cluster barrier per step: h(s) visible in everyone's A_next
        asm volatile("barrier.cluster.arrive.aligned;" ::: "memory");
        asm volatile("barrier.cluster.wait.aligned;" ::: "memory");
    }
}

extern "C" void kernel_launch(void* const* d_in, const int* in_sizes, int n_in,
                              void* d_out, int out_size) {
    const float* x    = (const float*)d_in[0];
    const float* W_is = (const float*)d_in[1];
    const float* b_is = (const float*)d_in[2];
    const float* W_ss = (const float*)d_in[3];
    const float* b_ss = (const float*)d_in[4];
    const float* h0   = (const float*)d_in[5];
    const float* c0   = (const float*)d_in[6];
    float* out = (float*)d_out;

    size_t smem = (size_t)SMEM_FLOATS * sizeof(float);
    cudaFuncSetAttribute(rowlstm_kernel,
                         cudaFuncAttributeMaxDynamicSharedMemorySize, (int)smem);
    rowlstm_kernel<<<NCTA, NTHR, smem>>>(x, W_is, b_is, W_ss, b_ss, h0, c0, out);
}

// round 7
// speedup vs baseline: 1.6512x; 1.6512x over previous
#include <cuda_runtime.h>
#include <cstdint>

#define BATCH 32
#define CIN   3
#define HH    64
#define WW    64
#define HC    128
#define NCTA  128
#define NTHR  256
#define CLU   4
#define AST   132                  // padded A row stride (floats): 528B = 4-bank skew

// smem layout (floats)
#define A0_OFF 0                   // (WW+1) x AST = 65*132 = 8580, row 0 = zero pad (w=-1)
#define A1_OFF 8580
#define W_OFF  17160               // 256 x 128: [(tap*128+ci)*128 + j_*8 + g*2 + p]
#define WI_OFF 49928               // 6 x 128:   [(tap*3+cn)*128 + j_*8 + g*2 + p]
#define SMEM_FLOATS 50696          // 202784 bytes

__device__ __forceinline__ unsigned long long pack2(float lo, float hi) {
    unsigned long long r;
    asm("mov.b64 %0, {%1, %2};" : "=l"(r) : "f"(lo), "f"(hi));
    return r;
}
__device__ __forceinline__ void unpack2(unsigned long long v, float& lo, float& hi) {
    asm("mov.b64 {%0, %1}, %2;" : "=f"(lo), "=f"(hi) : "l"(v));
}
__device__ __forceinline__ unsigned long long fma2(unsigned long long a,
                                                   unsigned long long b,
                                                   unsigned long long c) {
    unsigned long long d;
    asm("fma.rn.f32x2 %0, %1, %2, %3;" : "=l"(d) : "l"(a), "l"(b), "l"(c));
    return d;
}
__device__ __forceinline__ float sigm(float v) { return 1.f / (1.f + __expf(-v)); }

__global__ __launch_bounds__(NTHR, 1) __cluster_dims__(CLU, 1, 1)
void rowlstm_kernel(const float* __restrict__ x,
                    const float* __restrict__ W_is,
                    const float* __restrict__ b_is,
                    const float* __restrict__ W_ss,
                    const float* __restrict__ b_ss,
                    const float* __restrict__ h0,
                    const float* __restrict__ c0,
                    float* __restrict__ out)
{
    extern __shared__ float sm[];
    float* W_s  = sm + W_OFF;
    float* WI_s = sm + WI_OFF;

    const int tid = threadIdx.x;
    const int b   = blockIdx.x >> 2;
    unsigned int rank;
    asm("mov.u32 %0, %%cluster_ctarank;" : "=r"(rank));
    const int t = (int)rank;                 // ci-tile 0..3

    // ---- one-time loads ----
    // W_s[(tap*128+ci)*128 + j_*8 + g*2 + p], col = g*32 + j_*2 + p (thread-contiguous 8)
    for (int idx = tid; idx < 32768; idx += NTHR) {
        int k = idx >> 7, r = idx & 127;
        int tap = k >> 7, ci = k & 127;
        int jj = r >> 3, q = r & 7;
        int g = q >> 1, p = q & 1;
        int co = g * HC + t * 32 + jj * 2 + p;
        W_s[idx] = W_ss[(co * HC + ci) * 3 + tap];
    }
    // WI_s[(tap*3+cn)*128 + j_*8 + g*2 + p]
    for (int idx = tid; idx < 768; idx += NTHR) {
        int k = idx >> 7, r = idx & 127;
        int tap = k / 3, cn = k - tap * 3;
        int jj = r >> 3, q = r & 7;
        int g = q >> 1, p = q & 1;
        int co = g * HC + t * 32 + jj * 2 + p;
        WI_s[idx] = W_is[(co * CIN + cn) * 3 + tap];
    }
    // A0 <- full h0 (all 128 ci), pad row 0 of both buffers zero
    for (int idx = tid; idx < 8192; idx += NTHR) {
        int w = idx >> 7, ci = idx & 127;
        sm[A0_OFF + (w + 1) * AST + ci] = h0[ci * WW + w];
    }
    for (int idx = tid; idx < AST; idx += NTHR) {
        sm[A0_OFF + idx] = 0.f;
        sm[A1_OFF + idx] = 0.f;
    }

    // warp-shaped mapping: warp spans 4 distinct j_, 8 distinct i_
    const int wid  = tid >> 5;
    const int lane = tid & 31;
    const int j_ = (wid & 3) * 4 + (lane >> 3);   // 0..15
    const int i_ = (wid >> 2) * 8 + (lane & 7);   // 0..15
    const int j2 = j_ << 1;
    const int j8 = j_ << 3;

    // per-thread persistent state: bias pairs + cell state registers
    unsigned long long bias2[4];
    #pragma unroll
    for (int g = 0; g < 4; g++) {
        int co = g * HC + t * 32 + j2;
        bias2[g] = pack2(b_is[co] + b_ss[co], b_is[co + 1] + b_ss[co + 1]);
    }
    float creg[4][2];
    #pragma unroll
    for (int wi = 0; wi < 4; wi++) {
        int w = wi * 16 + i_;
        creg[wi][0] = c0[(t * 32 + j2) * WW + w];
        creg[wi][1] = c0[(t * 32 + j2 + 1) * WW + w];
    }

    // peer smem base addresses (shared::cluster window) for DSMEM h exchange
    unsigned int mybase;
    asm("{ .reg .u64 a; cvta.to.shared.u64 a, %1; cvt.u32.u64 %0, a; }"
        : "=r"(mybase) : "l"(sm));
    unsigned int peer[CLU];
    #pragma unroll
    for (int r = 0; r < CLU; r++)
        asm("mapa.shared::cluster.u32 %0, %1, %2;" : "=r"(peer[r]) : "r"(mybase), "r"(r));

    __syncthreads();   // local init (W_s, WI_s, A0) visible block-wide

    for (int s = 0; s < HH; s++) {
        const float* Ac = sm + ((s & 1) ? A1_OFF : A0_OFF);
        const unsigned int nextOffB = (unsigned int)(((s & 1) ? A0_OFF : A1_OFF) * 4);

        // ---- acc starts at bias, add x-projection (LDGs overlap following GEMM) ----
        unsigned long long acc[4][4];
        #pragma unroll
        for (int wi = 0; wi < 4; wi++)
            #pragma unroll
            for (int g = 0; g < 4; g++) acc[wi][g] = bias2[g];

        {
            float xr[4][3][2];
            #pragma unroll
            for (int wi = 0; wi < 4; wi++) {
                int w = wi * 16 + i_;
                #pragma unroll
                for (int cn = 0; cn < CIN; cn++) {
                    const float* xb = x + ((b * CIN + cn) * HH + s) * WW;
                    xr[wi][cn][0] = (w > 0) ? xb[w - 1] : 0.f;
                    xr[wi][cn][1] = xb[w];
                }
            }
            #pragma unroll
            for (int tap = 0; tap < 2; tap++)
                #pragma unroll
                for (int cn = 0; cn < CIN; cn++) {
                    const float* wr = WI_s + (tap * 3 + cn) * 128 + j8;
                    ulonglong2 wa  = *(const ulonglong2*)wr;        // gates 0,1
                    ulonglong2 wb2 = *(const ulonglong2*)(wr + 4);  // gates 2,3
                    #pragma unroll
                    for (int wi = 0; wi < 4; wi++) {
                        unsigned long long xp = pack2(xr[wi][cn][tap], xr[wi][cn][tap]);
                        acc[wi][0] = fma2(xp, wa.x,  acc[wi][0]);
                        acc[wi][1] = fma2(xp, wa.y,  acc[wi][1]);
                        acc[wi][2] = fma2(xp, wb2.x, acc[wi][2]);
                        acc[wi][3] = fma2(xp, wb2.y, acc[wi][3]);
                    }
                }
        }

        // ---- GEMM: (4 w) x (4 gates x 2 ci) over K = 2 taps x 128 ci ----
        for (int cb = 0; cb < HC; cb += 4) {
            float4 aL4[4], aC4[4];
            #pragma unroll
            for (int wi = 0; wi < 4; wi++) {
                int wp = wi * 16 + i_;
                aL4[wi] = *(const float4*)(Ac + wp * AST + cb);
                aC4[wi] = *(const float4*)(Ac + (wp + 1) * AST + cb);
            }
            #pragma unroll
            for (int u = 0; u < 4; u++) {
                const float* wr0 = W_s + (cb + u) * 128 + j8;
                const float* wr1 = wr0 + 128 * 128;
                ulonglong2 w0a = *(const ulonglong2*)wr0;        // tap0 gates 0,1
                ulonglong2 w0b = *(const ulonglong2*)(wr0 + 4);  // tap0 gates 2,3
                ulonglong2 w1a = *(const ulonglong2*)wr1;        // tap1 gates 0,1
                ulonglong2 w1b = *(const ulonglong2*)(wr1 + 4);  // tap1 gates 2,3
                #pragma unroll
                for (int wi = 0; wi < 4; wi++) {
                    float aL = ((const float*)&aL4[wi])[u];
                    float aC = ((const float*)&aC4[wi])[u];
                    unsigned long long aLp = pack2(aL, aL);
                    unsigned long long aCp = pack2(aC, aC);
                    acc[wi][0] = fma2(aLp, w0a.x, acc[wi][0]);
                    acc[wi][1] = fma2(aLp, w0a.y, acc[wi][1]);
                    acc[wi][2] = fma2(aLp, w0b.x, acc[wi][2]);
                    acc[wi][3] = fma2(aLp, w0b.y, acc[wi][3]);
                    acc[wi][0] = fma2(aCp, w1a.x, acc[wi][0]);
                    acc[wi][1] = fma2(aCp, w1a.y, acc[wi][1]);
                    acc[wi][2] = fma2(aCp, w1b.x, acc[wi][2]);
                    acc[wi][3] = fma2(aCp, w1b.y, acc[wi][3]);
                }
            }
        }

        // ---- gates -> c,h in registers; write out + h to all 4 cluster CTAs ----
        #pragma unroll
        for (int wi = 0; wi < 4; wi++) {
            int w = wi * 16 + i_;
            float gv[4][2];
            #pragma unroll
            for (int g = 0; g < 4; g++) {
                float a0, a1;
                unpack2(acc[wi][g], a0, a1);
                gv[g][0] = sigm(a0);
                gv[g][1] = sigm(a1);
            }
            float hp[2];
            #pragma unroll
            for (int p = 0; p < 2; p++) {
                float cn2 = gv[1][p] * creg[wi][p] + gv[2][p] * gv[3][p];
                creg[wi][p] = cn2;
                float h = gv[0][p] * tanhf(cn2);
                hp[p] = h;
                out[((b * HC + t * 32 + j2 + p) * HH + s) * WW + w] = h;
            }
            unsigned long long hpair = pack2(hp[0], hp[1]);
            unsigned int off = nextOffB + (unsigned int)(((w + 1) * AST + t * 32 + j2) * 4);
            #pragma unroll
            for (int r = 0; r < CLU; r++)
                asm volatile("st.shared::cluster.b64 [%0], %1;"
                             :: "r"(peer[r] + off), "l"(hpair) : "memory");
        }

        // one cluster barrier per step: h(s) visible in everyone's A_next
        asm volatile("barrier.cluster.arrive.aligned;" ::: "memory");
        asm volatile("barrier.cluster.wait.aligned;" ::: "memory");
    }
}

extern "C" void kernel_launch(void* const* d_in, const int* in_sizes, int n_in,
                              void* d_out, int out_size) {
    const float* x    = (const float*)d_in[0];
    const float* W_is = (const float*)d_in[1];
    const float* b_is = (const float*)d_in[2];
    const float* W_ss = (const float*)d_in[3];
    const float* b_ss = (const float*)d_in[4];
    const float* h0   = (const float*)d_in[5];
    const float* c0   = (const float*)d_in[6];
    float* out = (float*)d_out;

    size_t smem = (size_t)SMEM_FLOATS * sizeof(float);
    cudaFuncSetAttribute(rowlstm_kernel,
                         cudaFuncAttributeMaxDynamicSharedMemorySize, (int)smem);
    rowlstm_kernel<<<NCTA, NTHR, smem>>>(x, W_is, b_is, W_ss, b_ss, h0, c0, out);
}